// round 14
// baseline (speedup 1.0000x reference)
#include <cuda_runtime.h>
#include <cuda_bf16.h>

// Problem constants
#define BATCH 16
#define SEQ   4096
#define HDIM  1024
#define HN    16      // heads
#define HD    64      // head dim

// ---------------------------------------------------------------------------
// Scratch (device globals: no allocation allowed)
// ---------------------------------------------------------------------------
__device__ float g_q[BATCH * HDIM];          // q = query @ Wq^T + bq
__device__ float g_wt[BATCH * HDIM * HN];    // wT[b][k][h], tf32-rounded
__device__ float g_c[BATCH * HN];            // (1/32) q_h . bk_h
__device__ float g_att[BATCH * SEQ * HN];    // softmax attention, tf32-rounded
__device__ float g_u[BATCH * HN * HDIM];     // u[b,h,:] = sum_s att * value_row
__device__ float g_A[BATCH * HN];            // A[b,h]   = sum_s att
__device__ float g_o1[BATCH * HDIM];         // out before final projection

// ---------------------------------------------------------------------------
// helpers
// ---------------------------------------------------------------------------
__device__ __forceinline__ unsigned smem_u32(const void* p) {
    unsigned a;
    asm("{ .reg .u64 t; cvta.to.shared.u64 t, %1; cvt.u32.u64 %0, t; }"
        : "=r"(a) : "l"(p));
    return a;
}
__device__ __forceinline__ void cp_async16(unsigned dst, const void* src) {
    asm volatile("cp.async.cg.shared.global [%0], [%1], 16;"
                 :: "r"(dst), "l"(src) : "memory");
}
__device__ __forceinline__ void cp_commit() {
    asm volatile("cp.async.commit_group;" ::: "memory");
}
__device__ __forceinline__ void cp_wait1() {
    asm volatile("cp.async.wait_group 1;" ::: "memory");
}
__device__ __forceinline__ unsigned f2tf32(float f) {
    unsigned r;
    asm("cvt.rna.tf32.f32 %0, %1;" : "=r"(r) : "f"(f));
    return r;
}
// mma.sync m16n8k8 tf32: D += A(16x8) * B(8x8)
__device__ __forceinline__ void mma_tf32(float* d, unsigned a0, unsigned a1,
                                         unsigned a2, unsigned a3,
                                         unsigned b0, unsigned b1) {
    asm("mma.sync.aligned.m16n8k8.row.col.f32.tf32.tf32.f32 "
        "{%0,%1,%2,%3}, {%4,%5,%6,%7}, {%8,%9}, {%0,%1,%2,%3};"
        : "+f"(d[0]), "+f"(d[1]), "+f"(d[2]), "+f"(d[3])
        : "r"(a0), "r"(a1), "r"(a2), "r"(a3), "r"(b0), "r"(b1));
}

// ---------------------------------------------------------------------------
// K1: q[b,i] = query[b,:] . Wq[i,:] + bq[i]   (warp per output)
// ---------------------------------------------------------------------------
__global__ void k1_q(const float* __restrict__ query,
                     const float* __restrict__ Wq,
                     const float* __restrict__ bq) {
    int gw   = (blockIdx.x * blockDim.x + threadIdx.x) >> 5;
    int lane = threadIdx.x & 31;
    if (gw >= BATCH * HDIM) return;
    int b = gw >> 10, i = gw & 1023;
    const float4* qr = (const float4*)(query + b * HDIM);
    const float4* wr = (const float4*)(Wq + (size_t)i * HDIM);
    float acc = 0.f;
#pragma unroll
    for (int t = 0; t < 8; t++) {
        float4 a = qr[t * 32 + lane];
        float4 w = wr[t * 32 + lane];
        acc += a.x * w.x + a.y * w.y + a.z * w.z + a.w * w.w;
    }
#pragma unroll
    for (int o = 16; o > 0; o >>= 1) acc += __shfl_xor_sync(~0u, acc, o);
    if (lane == 0) g_q[gw] = acc + bq[i];
}

// ---------------------------------------------------------------------------
// K2: wT[b][j][h] = tf32( (1/32) sum_d q[b,h*64+d] * Wk[h*64+d, j] )
//     also zeros g_u and g_A.  block per (h,b), 256 threads.
// ---------------------------------------------------------------------------
__global__ void k2_w(const float* __restrict__ Wk,
                     const float* __restrict__ bk) {
    int h = blockIdx.x >> 4;
    int b = blockIdx.x & 15;
    int tid = threadIdx.x;

    int gtid = blockIdx.x * 256 + tid;
    ((float4*)g_u)[gtid] = make_float4(0.f, 0.f, 0.f, 0.f);
    if (gtid < BATCH * HN) g_A[gtid] = 0.f;

    __shared__ float qh[HD];
    if (tid < HD) qh[tid] = g_q[b * HDIM + h * HD + tid];
    __syncthreads();

    float4 acc = make_float4(0.f, 0.f, 0.f, 0.f);
    const float4* wk = (const float4*)(Wk + (size_t)(h * HD) * HDIM) + tid;
#pragma unroll 8
    for (int d = 0; d < HD; d++) {
        float4 v = wk[d * 256];
        float  s = qh[d];
        acc.x += s * v.x; acc.y += s * v.y; acc.z += s * v.z; acc.w += s * v.w;
    }
    const float scale = 0.03125f;  // 1/sqrt(1024)
    float* wrow = g_wt + ((size_t)b * HDIM + tid * 4) * HN + h;
    wrow[0 * HN] = __uint_as_float(f2tf32(acc.x * scale));
    wrow[1 * HN] = __uint_as_float(f2tf32(acc.y * scale));
    wrow[2 * HN] = __uint_as_float(f2tf32(acc.z * scale));
    wrow[3 * HN] = __uint_as_float(f2tf32(acc.w * scale));

    if (tid == 0) {
        float cc = 0.f;
        for (int d = 0; d < HD; d++) cc += qh[d] * bk[h * HD + d];
        g_c[b * HN + h] = cc * scale;
    }
}

// ---------------------------------------------------------------------------
// K3a TENSOR (R13-proven): scores[128,16] per CTA via mma.m16n8k8.tf32.
//  Quarter-sized grid (8 rblk, 16 b); q selects seq quarter.
// ---------------------------------------------------------------------------
#define KTS 36    // ktile row stride (floats), chunk width 32
#define WTS 24    // wtile row stride (floats)
__global__ __launch_bounds__(256, 3)
void k3a_scores(const float* __restrict__ key, int q) {
    extern __shared__ float sm[];
    float* kt   = sm;                        // 3 x 128 x 36
    float* wt   = kt + 3 * 128 * KTS;        // 3 x 32 x 24
    float* scor = wt + 3 * 32 * WTS;         // 128 x 17
    float* c_s  = scor + 128 * 17;           // 16
    float* A_s  = c_s + 16;                  // 16

    const int b    = blockIdx.y;
    const int row0 = (q * 8 + blockIdx.x) * 128;
    const int tid  = threadIdx.x;
    const int w    = tid >> 5;
    const int l    = tid & 31;
    const int g    = l >> 2;       // 0..7
    const int t4   = l & 3;        // 0..3

    if (tid < HN) { c_s[tid] = g_c[b * HN + tid]; A_s[tid] = 0.f; }

    const float* keyb = key + ((size_t)b * SEQ + row0) * HDIM;
    const float* wtb  = g_wt + (size_t)b * HDIM * HN;
    const unsigned kt_a = smem_u32(kt);
    const unsigned wt_a = smem_u32(wt);

    auto load_chunk = [&](int ch, int slot) {
        const int krow = tid >> 1;                 // 0..127
        const int seg  = tid & 1;                  // halves of 32 floats
        const float* srow = keyb + (size_t)krow * HDIM + ch * 32 + seg * 16;
        const unsigned drow = kt_a + (slot * 128 * KTS + krow * KTS + seg * 16) * 4;
#pragma unroll
        for (int i = 0; i < 4; i++)
            cp_async16(drow + i * 16, srow + i * 4);
        if (tid < 128) {
            const int wr = tid >> 2, sg = tid & 3; // wr 0..31
            cp_async16(wt_a + (slot * 32 * WTS + wr * WTS + sg * 4) * 4,
                       wtb + (size_t)(ch * 32 + wr) * HN + sg * 4);
        }
    };

    load_chunk(0, 0); cp_commit();
    load_chunk(1, 1); cp_commit();

    float d[2][4] = {{0.f, 0.f, 0.f, 0.f}, {0.f, 0.f, 0.f, 0.f}};

    for (int ch = 0; ch < 32; ch++) {
        cp_wait1();          // g_ch done (g_{ch+1} may pend)
        __syncthreads();     // data visible; all warps finished chunk ch-1

        if (ch + 2 < 32) load_chunk(ch + 2, (ch + 2) % 3);
        cp_commit();         // commit every iter: exact group counting

        const int slot = ch % 3;
        const float* kbase = kt + slot * 128 * KTS + (w * 16 + g) * KTS + t4;
        const float* wbase = wt + slot * 32 * WTS;
#pragma unroll
        for (int kk = 0; kk < 4; kk++) {
            unsigned a0 = __float_as_uint(kbase[kk * 8]);
            unsigned a1 = __float_as_uint(kbase[8 * KTS + kk * 8]);
            unsigned a2 = __float_as_uint(kbase[kk * 8 + 4]);
            unsigned a3 = __float_as_uint(kbase[8 * KTS + kk * 8 + 4]);
            unsigned b0 = __float_as_uint(wbase[(kk * 8 + t4) * WTS + g]);
            unsigned b1 = __float_as_uint(wbase[(kk * 8 + t4 + 4) * WTS + g]);
            unsigned b2 = __float_as_uint(wbase[(kk * 8 + t4) * WTS + 8 + g]);
            unsigned b3 = __float_as_uint(wbase[(kk * 8 + t4 + 4) * WTS + 8 + g]);
            mma_tf32(d[0], a0, a1, a2, a3, b0, b1);
            mma_tf32(d[1], a0, a1, a2, a3, b2, b3);
        }
    }
    __syncthreads();

    // write D to scor[row][head]
#pragma unroll
    for (int nt = 0; nt < 2; nt++) {
        scor[(w * 16 + g) * 17 + nt * 8 + t4 * 2 + 0] = d[nt][0];
        scor[(w * 16 + g) * 17 + nt * 8 + t4 * 2 + 1] = d[nt][1];
        scor[(w * 16 + g + 8) * 17 + nt * 8 + t4 * 2 + 0] = d[nt][2];
        scor[(w * 16 + g + 8) * 17 + nt * 8 + t4 * 2 + 1] = d[nt][3];
    }
    __syncthreads();

    // softmax over heads + att store (tf32-rounded) + A accumulation
    float* attb = g_att + ((size_t)b * SEQ + row0) * HN;
#pragma unroll
    for (int it = 0; it < 8; it++) {
        const int row = it * 16 + (tid >> 4);
        const int hh  = tid & 15;
        float sc = scor[row * 17 + hh] + c_s[hh];
        float m = sc;
#pragma unroll
        for (int o = 8; o > 0; o >>= 1) m = fmaxf(m, __shfl_xor_sync(~0u, m, o));
        float e = __expf(sc - m);
        float sum = e;
#pragma unroll
        for (int o = 8; o > 0; o >>= 1) sum += __shfl_xor_sync(~0u, sum, o);
        float att = __fdividef(e, sum);
        attb[row * HN + hh] = __uint_as_float(f2tf32(att));
        atomicAdd(&A_s[hh], att);
    }
    __syncthreads();
    if (tid < HN) atomicAdd(&g_A[b * HN + tid], A_s[tid]);
}

// ---------------------------------------------------------------------------
// K3b TENSOR (R13-proven): u partial = attT[16,1024q] @ value[1024q,1024].
//  Quarter-sized: grid (16 jc, 16 b), 16 stages of 64 rows; q selects quarter.
//  atomicAdd epilogue (4 quarter contenders per address).
// ---------------------------------------------------------------------------
#define VTS 72
#define ATS 24
__global__ __launch_bounds__(256, 4)
void k3b_tensor(const float* __restrict__ value, int q) {
    extern __shared__ float sm[];
    float* vt = sm;                    // 2 x 64 x 72
    float* at = vt + 2 * 64 * VTS;     // 2 x 64 x 24

    const int b   = blockIdx.y;
    const int jc  = blockIdx.x;        // 0..15
    const int j0  = jc * 64;
    const int tid = threadIdx.x;
    const int w   = tid >> 5;
    const int l   = tid & 31;
    const int g   = l >> 2;            // 0..7
    const int t4  = l & 3;             // 0..3

    const float* valb = value + ((size_t)b * SEQ + q * 1024) * HDIM + j0;
    const float* attb = g_att + ((size_t)b * SEQ + q * 1024) * HN;
    const unsigned vt_a = smem_u32(vt);
    const unsigned at_a = smem_u32(at);

    auto load_stage = [&](int st, int buf) {
        const int row = tid >> 2;      // 0..63
        const int seg = tid & 3;       // 0..3, 16 floats each
        const float* vsrc = valb + (size_t)(st * 64 + row) * HDIM + seg * 16;
        const unsigned vdst = vt_a + (buf * 64 * VTS + row * VTS + seg * 16) * 4;
        cp_async16(vdst,      vsrc);
        cp_async16(vdst + 16, vsrc + 4);
        cp_async16(vdst + 32, vsrc + 8);
        cp_async16(vdst + 48, vsrc + 12);
        cp_async16(at_a + (buf * 64 * ATS + row * ATS + seg * 4) * 4,
                   attb + (size_t)(st * 64 + row) * HN + seg * 4);
    };

    load_stage(0, 0);
    cp_commit();

    float d[4] = {0.f, 0.f, 0.f, 0.f};

    for (int st = 0; st < 16; st++) {
        __syncthreads();               // everyone done computing st-1
        if (st + 1 < 16) load_stage(st + 1, (st + 1) & 1);
        cp_commit();
        cp_wait1();                    // g_st done
        __syncthreads();               // visibility of stage st data

        const int buf = st & 1;
        const float* ab = at + buf * 64 * ATS;
        const float* vb = vt + buf * 64 * VTS + w * 8;
#pragma unroll
        for (int kk = 0; kk < 8; kk++) {
            const float* arow = ab + (kk * 8 + t4) * ATS;
            unsigned a0 = __float_as_uint(arow[g]);
            unsigned a1 = __float_as_uint(arow[g + 8]);
            unsigned a2 = __float_as_uint(arow[4 * ATS + g]);
            unsigned a3 = __float_as_uint(arow[4 * ATS + g + 8]);
            unsigned v0 = f2tf32(vb[(kk * 8 + t4) * VTS + g]);
            unsigned v1 = f2tf32(vb[(kk * 8 + t4 + 4) * VTS + g]);
            mma_tf32(d, a0, a1, a2, a3, v0, v1);
        }
    }

    // epilogue: atomicAdd (4 quarter contenders per address)
    const int j = j0 + w * 8 + t4 * 2;
    float* u0 = g_u + ((size_t)(b * HN + g)) * HDIM + j;
    float* u1 = g_u + ((size_t)(b * HN + g + 8)) * HDIM + j;
    atomicAdd(u0 + 0, d[0]);
    atomicAdd(u0 + 1, d[1]);
    atomicAdd(u1 + 0, d[2]);
    atomicAdd(u1 + 1, d[3]);
}

// ---------------------------------------------------------------------------
// K4: o1[b,j] = Wv[j,:] . u[b, j/64, :] + bv[j] * A[b, j/64]   warp per (j,b)
// ---------------------------------------------------------------------------
__global__ void k4_out(const float* __restrict__ Wv,
                       const float* __restrict__ bv) {
    int gw   = (blockIdx.x * blockDim.x + threadIdx.x) >> 5;
    int lane = threadIdx.x & 31;
    if (gw >= HDIM * BATCH) return;
    int b = gw & 15, j = gw >> 4, h = j >> 6;
    const float4* wr = (const float4*)(Wv + (size_t)j * HDIM);
    const float4* ur = (const float4*)(g_u + (b * HN + h) * HDIM);
    float acc = 0.f;
#pragma unroll
    for (int t = 0; t < 8; t++) {
        float4 w = wr[t * 32 + lane];
        float4 u = ur[t * 32 + lane];
        acc += w.x * u.x + w.y * u.y + w.z * u.z + w.w * u.w;
    }
#pragma unroll
    for (int o = 16; o > 0; o >>= 1) acc += __shfl_xor_sync(~0u, acc, o);
    if (lane == 0) g_o1[b * HDIM + j] = acc + bv[j] * g_A[b * HN + h];
}

// ---------------------------------------------------------------------------
// K5: res[b,i] = Wf[i,:] . o1[b,:] + bf[i]   warp per (i,b)
// ---------------------------------------------------------------------------
__global__ void k5_final(const float* __restrict__ Wf,
                         const float* __restrict__ bf,
                         float* __restrict__ res) {
    int gw   = (blockIdx.x * blockDim.x + threadIdx.x) >> 5;
    int lane = threadIdx.x & 31;
    if (gw >= HDIM * BATCH) return;
    int b = gw & 15, i = gw >> 4;
    const float4* wr = (const float4*)(Wf + (size_t)i * HDIM);
    const float4* orow = (const float4*)(g_o1 + b * HDIM);
    float acc = 0.f;
#pragma unroll
    for (int t = 0; t < 8; t++) {
        float4 w = wr[t * 32 + lane];
        float4 o = orow[t * 32 + lane];
        acc += w.x * o.x + w.y * o.y + w.z * o.z + w.w * o.w;
    }
#pragma unroll
    for (int o = 16; o > 0; o >>= 1) acc += __shfl_xor_sync(~0u, acc, o);
    if (lane == 0) res[b * HDIM + i] = acc + bf[i];
}

// ---------------------------------------------------------------------------
// launch: k3a/k3b software pipeline across two streams (fork/join events).
//  Streams + events created once on the eager correctness call (pre-capture);
//  captured calls only record/wait events — graph-capturable fork/join.
// ---------------------------------------------------------------------------
extern "C" void kernel_launch(void* const* d_in, const int* in_sizes, int n_in,
                              void* d_out, int out_size) {
    const float* query = (const float*)d_in[0];
    const float* key_  = (const float*)d_in[1];
    const float* value = (const float*)d_in[2];
    const float* Wq    = (const float*)d_in[3];
    const float* bq    = (const float*)d_in[4];
    const float* Wk    = (const float*)d_in[5];
    const float* bk    = (const float*)d_in[6];
    const float* Wv    = (const float*)d_in[7];
    const float* bv    = (const float*)d_in[8];
    const float* Wf    = (const float*)d_in[9];
    const float* bf    = (const float*)d_in[10];
    float* out = (float*)d_out;

    const int k3a_smem = (3 * 128 * KTS + 3 * 32 * WTS + 128 * 17 + 32) * 4;  // 73344 B
    const int k3b_smem = (2 * 64 * VTS + 2 * 64 * ATS) * 4;                   // 49152 B

    static bool init = false;
    static cudaStream_t side;
    static cudaEvent_t evA[4], evDone;
    if (!init) {
        cudaFuncSetAttribute(k3a_scores, cudaFuncAttributeMaxDynamicSharedMemorySize, k3a_smem);
        cudaFuncSetAttribute(k3b_tensor, cudaFuncAttributeMaxDynamicSharedMemorySize, k3b_smem);
        cudaStreamCreateWithFlags(&side, cudaStreamNonBlocking);
        for (int i = 0; i < 4; i++)
            cudaEventCreateWithFlags(&evA[i], cudaEventDisableTiming);
        cudaEventCreateWithFlags(&evDone, cudaEventDisableTiming);
        init = true;
    }

    k1_q<<<(BATCH * HDIM * 32 + 255) / 256, 256>>>(query, Wq, bq);
    k2_w<<<HN * BATCH, 256>>>(Wk, bk);

    // pipelined k3a (main stream) / k3b (side stream) over 4 seq quarters
    for (int q = 0; q < 4; q++) {
        dim3 grid_a(8, BATCH);
        k3a_scores<<<grid_a, 256, k3a_smem>>>(key_, q);
        cudaEventRecord(evA[q], 0);
    }
    for (int q = 0; q < 4; q++) {
        cudaStreamWaitEvent(side, evA[q], 0);
        dim3 grid_b(HDIM / 64, BATCH);
        k3b_tensor<<<grid_b, 256, k3b_smem, side>>>(value, q);
    }
    cudaEventRecord(evDone, side);
    cudaStreamWaitEvent(0, evDone, 0);

    k4_out<<<(HDIM * BATCH * 32 + 255) / 256, 256>>>(Wv, bv);
    k5_final<<<(HDIM * BATCH * 32 + 255) / 256, 256>>>(Wf, bf, out);
}

// round 15
// speedup vs baseline: 1.6721x; 1.6721x over previous
#include <cuda_runtime.h>
#include <cuda_bf16.h>

// Problem constants
#define BATCH 16
#define SEQ   4096
#define HDIM  1024
#define HN    16      // heads
#define HD    64      // head dim

// ---------------------------------------------------------------------------
// Scratch (device globals: no allocation allowed)
// ---------------------------------------------------------------------------
__device__ float g_q[BATCH * HDIM];          // q = query @ Wq^T + bq
__device__ float g_wt[BATCH * HDIM * HN];    // wT[b][k][h], tf32-rounded
__device__ float g_c[BATCH * HN];            // (1/32) q_h . bk_h
__device__ float g_att[BATCH * SEQ * HN];    // softmax attention, tf32-rounded
__device__ float g_u[BATCH * HN * HDIM];     // u[b,h,:] = sum_s att * value_row
__device__ float g_A[BATCH * HN];            // A[b,h]   = sum_s att
__device__ float g_o1[BATCH * HDIM];         // out before final projection

// ---------------------------------------------------------------------------
// helpers
// ---------------------------------------------------------------------------
__device__ __forceinline__ unsigned smem_u32(const void* p) {
    unsigned a;
    asm("{ .reg .u64 t; cvta.to.shared.u64 t, %1; cvt.u32.u64 %0, t; }"
        : "=r"(a) : "l"(p));
    return a;
}
__device__ __forceinline__ void cp_async16(unsigned dst, const void* src) {
    asm volatile("cp.async.cg.shared.global [%0], [%1], 16;"
                 :: "r"(dst), "l"(src) : "memory");
}
__device__ __forceinline__ void cp_commit() {
    asm volatile("cp.async.commit_group;" ::: "memory");
}
__device__ __forceinline__ void cp_wait1() {
    asm volatile("cp.async.wait_group 1;" ::: "memory");
}
__device__ __forceinline__ unsigned f2tf32(float f) {
    unsigned r;
    asm("cvt.rna.tf32.f32 %0, %1;" : "=r"(r) : "f"(f));
    return r;
}
// mma.sync m16n8k8 tf32: D += A(16x8) * B(8x8)
__device__ __forceinline__ void mma_tf32(float* d, unsigned a0, unsigned a1,
                                         unsigned a2, unsigned a3,
                                         unsigned b0, unsigned b1) {
    asm("mma.sync.aligned.m16n8k8.row.col.f32.tf32.tf32.f32 "
        "{%0,%1,%2,%3}, {%4,%5,%6,%7}, {%8,%9}, {%0,%1,%2,%3};"
        : "+f"(d[0]), "+f"(d[1]), "+f"(d[2]), "+f"(d[3])
        : "r"(a0), "r"(a1), "r"(a2), "r"(a3), "r"(b0), "r"(b1));
}
// f32x2 packed FMA helpers (scalar k3b)
__device__ __forceinline__ void fma2(unsigned long long &d,
                                     unsigned long long a,
                                     unsigned long long b) {
    asm("fma.rn.f32x2 %0, %1, %2, %0;" : "+l"(d) : "l"(a), "l"(b));
}
__device__ __forceinline__ float2 unpack2(unsigned long long v) {
    float2 f;
    asm("mov.b64 {%0, %1}, %2;" : "=f"(f.x), "=f"(f.y) : "l"(v));
    return f;
}
__device__ __forceinline__ unsigned long long pack_dup(float a) {
    unsigned long long r;
    asm("mov.b64 %0, {%1, %1};" : "=l"(r) : "f"(a));
    return r;
}

// ---------------------------------------------------------------------------
// K1: q[b,i] = query[b,:] . Wq[i,:] + bq[i]   (warp per output)
// ---------------------------------------------------------------------------
__global__ void k1_q(const float* __restrict__ query,
                     const float* __restrict__ Wq,
                     const float* __restrict__ bq) {
    int gw   = (blockIdx.x * blockDim.x + threadIdx.x) >> 5;
    int lane = threadIdx.x & 31;
    if (gw >= BATCH * HDIM) return;
    int b = gw >> 10, i = gw & 1023;
    const float4* qr = (const float4*)(query + b * HDIM);
    const float4* wr = (const float4*)(Wq + (size_t)i * HDIM);
    float acc = 0.f;
#pragma unroll
    for (int t = 0; t < 8; t++) {
        float4 a = qr[t * 32 + lane];
        float4 w = wr[t * 32 + lane];
        acc += a.x * w.x + a.y * w.y + a.z * w.z + a.w * w.w;
    }
#pragma unroll
    for (int o = 16; o > 0; o >>= 1) acc += __shfl_xor_sync(~0u, acc, o);
    if (lane == 0) g_q[gw] = acc + bq[i];
}

// ---------------------------------------------------------------------------
// K2: wT[b][j][h] = tf32( (1/32) sum_d q[b,h*64+d] * Wk[h*64+d, j] )
//     also zeros g_u and g_A.  block per (h,b), 256 threads.
// ---------------------------------------------------------------------------
__global__ void k2_w(const float* __restrict__ Wk,
                     const float* __restrict__ bk) {
    int h = blockIdx.x >> 4;
    int b = blockIdx.x & 15;
    int tid = threadIdx.x;

    int gtid = blockIdx.x * 256 + tid;
    ((float4*)g_u)[gtid] = make_float4(0.f, 0.f, 0.f, 0.f);
    if (gtid < BATCH * HN) g_A[gtid] = 0.f;

    __shared__ float qh[HD];
    if (tid < HD) qh[tid] = g_q[b * HDIM + h * HD + tid];
    __syncthreads();

    float4 acc = make_float4(0.f, 0.f, 0.f, 0.f);
    const float4* wk = (const float4*)(Wk + (size_t)(h * HD) * HDIM) + tid;
#pragma unroll 8
    for (int d = 0; d < HD; d++) {
        float4 v = wk[d * 256];
        float  s = qh[d];
        acc.x += s * v.x; acc.y += s * v.y; acc.z += s * v.z; acc.w += s * v.w;
    }
    const float scale = 0.03125f;  // 1/sqrt(1024)
    float* wrow = g_wt + ((size_t)b * HDIM + tid * 4) * HN + h;
    wrow[0 * HN] = __uint_as_float(f2tf32(acc.x * scale));
    wrow[1 * HN] = __uint_as_float(f2tf32(acc.y * scale));
    wrow[2 * HN] = __uint_as_float(f2tf32(acc.z * scale));
    wrow[3 * HN] = __uint_as_float(f2tf32(acc.w * scale));

    if (tid == 0) {
        float cc = 0.f;
        for (int d = 0; d < HD; d++) cc += qh[d] * bk[h * HD + d];
        g_c[b * HN + h] = cc * scale;
    }
}

// ---------------------------------------------------------------------------
// K3a TENSOR (R13-proven, fastest measured): scores[128,16] per CTA.
//  3-slot ring, ONE __syncthreads per chunk, 3 CTA/SM, chunk width 32,
//  raw f32 key bits as tf32 A-operands. Accumulates g_A.
// ---------------------------------------------------------------------------
#define KTS 36    // ktile row stride (floats), chunk width 32
#define WTS 24    // wtile row stride (floats)
__global__ __launch_bounds__(256, 3)
void k3a_scores(const float* __restrict__ key) {
    extern __shared__ float sm[];
    float* kt   = sm;                        // 3 x 128 x 36
    float* wt   = kt + 3 * 128 * KTS;        // 3 x 32 x 24
    float* scor = wt + 3 * 32 * WTS;         // 128 x 17
    float* c_s  = scor + 128 * 17;           // 16
    float* A_s  = c_s + 16;                  // 16

    const int b    = blockIdx.y;
    const int row0 = blockIdx.x * 128;
    const int tid  = threadIdx.x;
    const int w    = tid >> 5;
    const int l    = tid & 31;
    const int g    = l >> 2;       // 0..7
    const int t4   = l & 3;        // 0..3

    if (tid < HN) { c_s[tid] = g_c[b * HN + tid]; A_s[tid] = 0.f; }

    const float* keyb = key + ((size_t)b * SEQ + row0) * HDIM;
    const float* wtb  = g_wt + (size_t)b * HDIM * HN;
    const unsigned kt_a = smem_u32(kt);
    const unsigned wt_a = smem_u32(wt);

    auto load_chunk = [&](int ch, int slot) {
        const int krow = tid >> 1;                 // 0..127
        const int seg  = tid & 1;                  // halves of 32 floats
        const float* srow = keyb + (size_t)krow * HDIM + ch * 32 + seg * 16;
        const unsigned drow = kt_a + (slot * 128 * KTS + krow * KTS + seg * 16) * 4;
#pragma unroll
        for (int i = 0; i < 4; i++)
            cp_async16(drow + i * 16, srow + i * 4);
        if (tid < 128) {
            const int wr = tid >> 2, sg = tid & 3; // wr 0..31
            cp_async16(wt_a + (slot * 32 * WTS + wr * WTS + sg * 4) * 4,
                       wtb + (size_t)(ch * 32 + wr) * HN + sg * 4);
        }
    };

    load_chunk(0, 0); cp_commit();
    load_chunk(1, 1); cp_commit();

    float d[2][4] = {{0.f, 0.f, 0.f, 0.f}, {0.f, 0.f, 0.f, 0.f}};

    for (int ch = 0; ch < 32; ch++) {
        cp_wait1();          // g_ch done (g_{ch+1} may pend)
        __syncthreads();     // data visible; all warps finished chunk ch-1

        if (ch + 2 < 32) load_chunk(ch + 2, (ch + 2) % 3);
        cp_commit();         // commit every iter: exact group counting

        const int slot = ch % 3;
        const float* kbase = kt + slot * 128 * KTS + (w * 16 + g) * KTS + t4;
        const float* wbase = wt + slot * 32 * WTS;
#pragma unroll
        for (int kk = 0; kk < 4; kk++) {
            unsigned a0 = __float_as_uint(kbase[kk * 8]);
            unsigned a1 = __float_as_uint(kbase[8 * KTS + kk * 8]);
            unsigned a2 = __float_as_uint(kbase[kk * 8 + 4]);
            unsigned a3 = __float_as_uint(kbase[8 * KTS + kk * 8 + 4]);
            unsigned b0 = __float_as_uint(wbase[(kk * 8 + t4) * WTS + g]);
            unsigned b1 = __float_as_uint(wbase[(kk * 8 + t4 + 4) * WTS + g]);
            unsigned b2 = __float_as_uint(wbase[(kk * 8 + t4) * WTS + 8 + g]);
            unsigned b3 = __float_as_uint(wbase[(kk * 8 + t4 + 4) * WTS + 8 + g]);
            mma_tf32(d[0], a0, a1, a2, a3, b0, b1);
            mma_tf32(d[1], a0, a1, a2, a3, b2, b3);
        }
    }
    __syncthreads();

    // write D to scor[row][head]
#pragma unroll
    for (int nt = 0; nt < 2; nt++) {
        scor[(w * 16 + g) * 17 + nt * 8 + t4 * 2 + 0] = d[nt][0];
        scor[(w * 16 + g) * 17 + nt * 8 + t4 * 2 + 1] = d[nt][1];
        scor[(w * 16 + g + 8) * 17 + nt * 8 + t4 * 2 + 0] = d[nt][2];
        scor[(w * 16 + g + 8) * 17 + nt * 8 + t4 * 2 + 1] = d[nt][3];
    }
    __syncthreads();

    // softmax over heads + att store (tf32-rounded) + A accumulation
    float* attb = g_att + ((size_t)b * SEQ + row0) * HN;
#pragma unroll
    for (int it = 0; it < 8; it++) {
        const int row = it * 16 + (tid >> 4);
        const int hh  = tid & 15;
        float sc = scor[row * 17 + hh] + c_s[hh];
        float m = sc;
#pragma unroll
        for (int o = 8; o > 0; o >>= 1) m = fmaxf(m, __shfl_xor_sync(~0u, m, o));
        float e = __expf(sc - m);
        float sum = e;
#pragma unroll
        for (int o = 8; o > 0; o >>= 1) sum += __shfl_xor_sync(~0u, sum, o);
        float att = __fdividef(e, sum);
        attb[row * HN + hh] = __uint_as_float(f2tf32(att));
        atomicAdd(&A_s[hh], att);
    }
    __syncthreads();
    if (tid < HN) atomicAdd(&g_A[b * HN + tid], A_s[tid]);
}

// ---------------------------------------------------------------------------
// K3b SCALAR (R9-proven, 71.4us — fastest measured):
//  u[b,h,j] += sum_s att[b,s,h] * value[b,s,j]
//  grid (16 chunks, 16 b), 256 thr, 2 CTA/SM, f32x2 FMA accumulators.
//  (A accumulation removed — k3a owns g_A now.)
// ---------------------------------------------------------------------------
__global__ __launch_bounds__(256, 2)
void k3b_accum(const float* __restrict__ value) {
    __shared__ unsigned long long att_s[512];   // 32 rows x 16 heads, packed {a,a}

    const int b = blockIdx.y;
    const int chunk = blockIdx.x;
    const int tid = threadIdx.x;
    const int wq = tid >> 5;
    const int lane = tid & 31;
    const int j0 = (wq << 7) + (lane << 2);

    const float* valb = value + (size_t)b * SEQ * HDIM;
    const float* attb = g_att + (size_t)b * SEQ * HN;
    const int row0 = chunk << 8;

    unsigned long long u2[32];
#pragma unroll
    for (int i = 0; i < 32; i++) u2[i] = 0ULL;

    for (int G = 0; G < 8; G++) {
        const int r32 = row0 + G * 32;
        {
            const float* asrc = attb + (size_t)r32 * HN;
            att_s[tid]       = pack_dup(asrc[tid]);
            att_s[tid + 256] = pack_dup(asrc[tid + 256]);
        }
        __syncthreads();

#pragma unroll
        for (int g4 = 0; g4 < 4; g4++) {
            const int rb = r32 + g4 * 8;
            ulonglong2 vv[8];
#pragma unroll
            for (int r = 0; r < 8; r++)
                vv[r] = *(const ulonglong2*)(valb + (size_t)(rb + r) * HDIM + j0);
#pragma unroll
            for (int r = 0; r < 8; r++) {
#pragma unroll
                for (int h = 0; h < 16; h++) {
                    unsigned long long a2 = att_s[(g4 * 8 + r) * 16 + h];
                    fma2(u2[2 * h + 0], a2, vv[r].x);
                    fma2(u2[2 * h + 1], a2, vv[r].y);
                }
            }
        }
        __syncthreads();
    }

    float* ubase = g_u + (b * HN) * HDIM + j0;
#pragma unroll
    for (int h = 0; h < 16; h++) {
        float2 lo = unpack2(u2[2 * h + 0]);
        float2 hi = unpack2(u2[2 * h + 1]);
        atomicAdd(ubase + (h << 10) + 0, lo.x);
        atomicAdd(ubase + (h << 10) + 1, lo.y);
        atomicAdd(ubase + (h << 10) + 2, hi.x);
        atomicAdd(ubase + (h << 10) + 3, hi.y);
    }
}

// ---------------------------------------------------------------------------
// K4: o1[b,j] = Wv[j,:] . u[b, j/64, :] + bv[j] * A[b, j/64]   warp per (j,b)
// ---------------------------------------------------------------------------
__global__ void k4_out(const float* __restrict__ Wv,
                       const float* __restrict__ bv) {
    int gw   = (blockIdx.x * blockDim.x + threadIdx.x) >> 5;
    int lane = threadIdx.x & 31;
    if (gw >= HDIM * BATCH) return;
    int b = gw & 15, j = gw >> 4, h = j >> 6;
    const float4* wr = (const float4*)(Wv + (size_t)j * HDIM);
    const float4* ur = (const float4*)(g_u + (b * HN + h) * HDIM);
    float acc = 0.f;
#pragma unroll
    for (int t = 0; t < 8; t++) {
        float4 w = wr[t * 32 + lane];
        float4 u = ur[t * 32 + lane];
        acc += w.x * u.x + w.y * u.y + w.z * u.z + w.w * u.w;
    }
#pragma unroll
    for (int o = 16; o > 0; o >>= 1) acc += __shfl_xor_sync(~0u, acc, o);
    if (lane == 0) g_o1[b * HDIM + j] = acc + bv[j] * g_A[b * HN + h];
}

// ---------------------------------------------------------------------------
// K5: res[b,i] = Wf[i,:] . o1[b,:] + bf[i]   warp per (i,b)
// ---------------------------------------------------------------------------
__global__ void k5_final(const float* __restrict__ Wf,
                         const float* __restrict__ bf,
                         float* __restrict__ res) {
    int gw   = (blockIdx.x * blockDim.x + threadIdx.x) >> 5;
    int lane = threadIdx.x & 31;
    if (gw >= HDIM * BATCH) return;
    int b = gw & 15, i = gw >> 4;
    const float4* wr = (const float4*)(Wf + (size_t)i * HDIM);
    const float4* orow = (const float4*)(g_o1 + b * HDIM);
    float acc = 0.f;
#pragma unroll
    for (int t = 0; t < 8; t++) {
        float4 w = wr[t * 32 + lane];
        float4 o = orow[t * 32 + lane];
        acc += w.x * o.x + w.y * o.y + w.z * o.z + w.w * o.w;
    }
#pragma unroll
    for (int o = 16; o > 0; o >>= 1) acc += __shfl_xor_sync(~0u, acc, o);
    if (lane == 0) res[b * HDIM + i] = acc + bf[i];
}

// ---------------------------------------------------------------------------
// launch (single stream; no splits — R14's quarter-split regressed)
// ---------------------------------------------------------------------------
extern "C" void kernel_launch(void* const* d_in, const int* in_sizes, int n_in,
                              void* d_out, int out_size) {
    const float* query = (const float*)d_in[0];
    const float* key_  = (const float*)d_in[1];
    const float* value = (const float*)d_in[2];
    const float* Wq    = (const float*)d_in[3];
    const float* bq    = (const float*)d_in[4];
    const float* Wk    = (const float*)d_in[5];
    const float* bk    = (const float*)d_in[6];
    const float* Wv    = (const float*)d_in[7];
    const float* bv    = (const float*)d_in[8];
    const float* Wf    = (const float*)d_in[9];
    const float* bf    = (const float*)d_in[10];
    float* out = (float*)d_out;

    const int k3a_smem = (3 * 128 * KTS + 3 * 32 * WTS + 128 * 17 + 32) * 4;  // 73344 B
    static bool attr_set = false;
    if (!attr_set) {
        cudaFuncSetAttribute(k3a_scores, cudaFuncAttributeMaxDynamicSharedMemorySize, k3a_smem);
        attr_set = true;
    }

    k1_q<<<(BATCH * HDIM * 32 + 255) / 256, 256>>>(query, Wq, bq);
    k2_w<<<HN * BATCH, 256>>>(Wk, bk);
    {
        dim3 grid_a(SEQ / 128, BATCH);
        k3a_scores<<<grid_a, 256, k3a_smem>>>(key_);
        dim3 grid_b(SEQ / 256, BATCH);
        k3b_accum<<<grid_b, 256>>>(value);
    }
    k4_out<<<(HDIM * BATCH * 32 + 255) / 256, 256>>>(Wv, bv);
    k5_final<<<(HDIM * BATCH * 32 + 255) / 256, 256>>>(Wf, bf, out);
}

// round 16
// speedup vs baseline: 1.6877x; 1.0093x over previous
#include <cuda_runtime.h>
#include <cuda_bf16.h>

// Problem constants
#define BATCH 16
#define SEQ   4096
#define HDIM  1024
#define HN    16      // heads
#define HD    64      // head dim

// ---------------------------------------------------------------------------
// Scratch (device globals: no allocation allowed)
// ---------------------------------------------------------------------------
__device__ float g_q[BATCH * HDIM];          // q = query @ Wq^T + bq
__device__ float g_wt[BATCH * HDIM * HN];    // wT[b][k][h], tf32-rounded
__device__ float g_c[BATCH * HN];            // (1/32) q_h . bk_h
__device__ float g_att[BATCH * SEQ * HN];    // softmax attention, tf32-rounded
__device__ float g_u[BATCH * HN * HDIM];     // u[b,h,:] = sum_s att * value_row
__device__ float g_A[BATCH * HN];            // A[b,h]   = sum_s att
__device__ float g_o1[BATCH * HDIM];         // out before final projection

// ---------------------------------------------------------------------------
// helpers
// ---------------------------------------------------------------------------
__device__ __forceinline__ unsigned smem_u32(const void* p) {
    unsigned a;
    asm("{ .reg .u64 t; cvta.to.shared.u64 t, %1; cvt.u32.u64 %0, t; }"
        : "=r"(a) : "l"(p));
    return a;
}
__device__ __forceinline__ void cp_async16(unsigned dst, const void* src) {
    asm volatile("cp.async.cg.shared.global [%0], [%1], 16;"
                 :: "r"(dst), "l"(src) : "memory");
}
__device__ __forceinline__ void cp_commit() {
    asm volatile("cp.async.commit_group;" ::: "memory");
}
__device__ __forceinline__ void cp_wait1() {
    asm volatile("cp.async.wait_group 1;" ::: "memory");
}
__device__ __forceinline__ unsigned f2tf32(float f) {
    unsigned r;
    asm("cvt.rna.tf32.f32 %0, %1;" : "=r"(r) : "f"(f));
    return r;
}
// mma.sync m16n8k8 tf32: D += A(16x8) * B(8x8)
__device__ __forceinline__ void mma_tf32(float* d, unsigned a0, unsigned a1,
                                         unsigned a2, unsigned a3,
                                         unsigned b0, unsigned b1) {
    asm("mma.sync.aligned.m16n8k8.row.col.f32.tf32.tf32.f32 "
        "{%0,%1,%2,%3}, {%4,%5,%6,%7}, {%8,%9}, {%0,%1,%2,%3};"
        : "+f"(d[0]), "+f"(d[1]), "+f"(d[2]), "+f"(d[3])
        : "r"(a0), "r"(a1), "r"(a2), "r"(a3), "r"(b0), "r"(b1));
}
// f32x2 packed FMA helpers (scalar k3b)
__device__ __forceinline__ void fma2(unsigned long long &d,
                                     unsigned long long a,
                                     unsigned long long b) {
    asm("fma.rn.f32x2 %0, %1, %2, %0;" : "+l"(d) : "l"(a), "l"(b));
}
__device__ __forceinline__ float2 unpack2(unsigned long long v) {
    float2 f;
    asm("mov.b64 {%0, %1}, %2;" : "=f"(f.x), "=f"(f.y) : "l"(v));
    return f;
}
__device__ __forceinline__ unsigned long long pack_dup(float a) {
    unsigned long long r;
    asm("mov.b64 %0, {%1, %1};" : "=l"(r) : "f"(a));
    return r;
}

// ---------------------------------------------------------------------------
// K1 v2: q[b,i] = query[b,:] . Wq[i,:] + bq[i]
//  warp per (i, b-half): Wq row register-resident, reused over 8 batches.
// ---------------------------------------------------------------------------
__global__ void k1_q(const float* __restrict__ query,
                     const float* __restrict__ Wq,
                     const float* __restrict__ bq) {
    int gw   = (blockIdx.x * blockDim.x + threadIdx.x) >> 5;
    int lane = threadIdx.x & 31;
    if (gw >= HDIM * 2) return;
    int i = gw >> 1, bh = gw & 1;
    float4 wq[8];
    const float4* wr = (const float4*)(Wq + (size_t)i * HDIM);
#pragma unroll
    for (int t = 0; t < 8; t++) wq[t] = wr[t * 32 + lane];
    float bqi = bq[i];
#pragma unroll
    for (int bb = 0; bb < 8; bb++) {
        int b = bh * 8 + bb;
        const float4* qr = (const float4*)(query + (size_t)b * HDIM);
        float acc = 0.f;
#pragma unroll
        for (int t = 0; t < 8; t++) {
            float4 a = qr[t * 32 + lane];
            acc += a.x * wq[t].x + a.y * wq[t].y + a.z * wq[t].z + a.w * wq[t].w;
        }
#pragma unroll
        for (int o = 16; o > 0; o >>= 1) acc += __shfl_xor_sync(~0u, acc, o);
        if (lane == 0) g_q[b * HDIM + i] = acc + bqi;
    }
}

// ---------------------------------------------------------------------------
// K2: wT[b][j][h] = tf32( (1/32) sum_d q[b,h*64+d] * Wk[h*64+d, j] )
//     also zeros g_u and g_A.  block per (h,b), 256 threads.
// ---------------------------------------------------------------------------
__global__ void k2_w(const float* __restrict__ Wk,
                     const float* __restrict__ bk) {
    int h = blockIdx.x >> 4;
    int b = blockIdx.x & 15;
    int tid = threadIdx.x;

    int gtid = blockIdx.x * 256 + tid;
    ((float4*)g_u)[gtid] = make_float4(0.f, 0.f, 0.f, 0.f);
    if (gtid < BATCH * HN) g_A[gtid] = 0.f;

    __shared__ float qh[HD];
    if (tid < HD) qh[tid] = g_q[b * HDIM + h * HD + tid];
    __syncthreads();

    float4 acc = make_float4(0.f, 0.f, 0.f, 0.f);
    const float4* wk = (const float4*)(Wk + (size_t)(h * HD) * HDIM) + tid;
#pragma unroll 8
    for (int d = 0; d < HD; d++) {
        float4 v = wk[d * 256];
        float  s = qh[d];
        acc.x += s * v.x; acc.y += s * v.y; acc.z += s * v.z; acc.w += s * v.w;
    }
    const float scale = 0.03125f;  // 1/sqrt(1024)
    float* wrow = g_wt + ((size_t)b * HDIM + tid * 4) * HN + h;
    wrow[0 * HN] = __uint_as_float(f2tf32(acc.x * scale));
    wrow[1 * HN] = __uint_as_float(f2tf32(acc.y * scale));
    wrow[2 * HN] = __uint_as_float(f2tf32(acc.z * scale));
    wrow[3 * HN] = __uint_as_float(f2tf32(acc.w * scale));

    if (tid == 0) {
        float cc = 0.f;
        for (int d = 0; d < HD; d++) cc += qh[d] * bk[h * HD + d];
        g_c[b * HN + h] = cc * scale;
    }
}

// ---------------------------------------------------------------------------
// K3a TENSOR (R13-proven): scores[128,16] per CTA via mma.m16n8k8.tf32.
//  3-slot ring, ONE __syncthreads per chunk, 3 CTA/SM, chunk width 32,
//  raw f32 key bits as tf32 A-operands. Accumulates g_A (local acc + 1 atomic).
// ---------------------------------------------------------------------------
#define KTS 36    // ktile row stride (floats), chunk width 32
#define WTS 24    // wtile row stride (floats)
__global__ __launch_bounds__(256, 3)
void k3a_scores(const float* __restrict__ key) {
    extern __shared__ float sm[];
    float* kt   = sm;                        // 3 x 128 x 36
    float* wt   = kt + 3 * 128 * KTS;        // 3 x 32 x 24
    float* scor = wt + 3 * 32 * WTS;         // 128 x 17
    float* c_s  = scor + 128 * 17;           // 16
    float* A_s  = c_s + 16;                  // 16

    const int b    = blockIdx.y;
    const int row0 = blockIdx.x * 128;
    const int tid  = threadIdx.x;
    const int w    = tid >> 5;
    const int l    = tid & 31;
    const int g    = l >> 2;       // 0..7
    const int t4   = l & 3;        // 0..3

    if (tid < HN) { c_s[tid] = g_c[b * HN + tid]; A_s[tid] = 0.f; }

    const float* keyb = key + ((size_t)b * SEQ + row0) * HDIM;
    const float* wtb  = g_wt + (size_t)b * HDIM * HN;
    const unsigned kt_a = smem_u32(kt);
    const unsigned wt_a = smem_u32(wt);

    auto load_chunk = [&](int ch, int slot) {
        const int krow = tid >> 1;                 // 0..127
        const int seg  = tid & 1;                  // halves of 32 floats
        const float* srow = keyb + (size_t)krow * HDIM + ch * 32 + seg * 16;
        const unsigned drow = kt_a + (slot * 128 * KTS + krow * KTS + seg * 16) * 4;
#pragma unroll
        for (int i = 0; i < 4; i++)
            cp_async16(drow + i * 16, srow + i * 4);
        if (tid < 128) {
            const int wr = tid >> 2, sg = tid & 3; // wr 0..31
            cp_async16(wt_a + (slot * 32 * WTS + wr * WTS + sg * 4) * 4,
                       wtb + (size_t)(ch * 32 + wr) * HN + sg * 4);
        }
    };

    load_chunk(0, 0); cp_commit();
    load_chunk(1, 1); cp_commit();

    float d[2][4] = {{0.f, 0.f, 0.f, 0.f}, {0.f, 0.f, 0.f, 0.f}};

    for (int ch = 0; ch < 32; ch++) {
        cp_wait1();          // g_ch done (g_{ch+1} may pend)
        __syncthreads();     // data visible; all warps finished chunk ch-1

        if (ch + 2 < 32) load_chunk(ch + 2, (ch + 2) % 3);
        cp_commit();         // commit every iter: exact group counting

        const int slot = ch % 3;
        const float* kbase = kt + slot * 128 * KTS + (w * 16 + g) * KTS + t4;
        const float* wbase = wt + slot * 32 * WTS;
#pragma unroll
        for (int kk = 0; kk < 4; kk++) {
            unsigned a0 = __float_as_uint(kbase[kk * 8]);
            unsigned a1 = __float_as_uint(kbase[8 * KTS + kk * 8]);
            unsigned a2 = __float_as_uint(kbase[kk * 8 + 4]);
            unsigned a3 = __float_as_uint(kbase[8 * KTS + kk * 8 + 4]);
            unsigned b0 = __float_as_uint(wbase[(kk * 8 + t4) * WTS + g]);
            unsigned b1 = __float_as_uint(wbase[(kk * 8 + t4 + 4) * WTS + g]);
            unsigned b2 = __float_as_uint(wbase[(kk * 8 + t4) * WTS + 8 + g]);
            unsigned b3 = __float_as_uint(wbase[(kk * 8 + t4 + 4) * WTS + 8 + g]);
            mma_tf32(d[0], a0, a1, a2, a3, b0, b1);
            mma_tf32(d[1], a0, a1, a2, a3, b2, b3);
        }
    }
    __syncthreads();

    // write D to scor[row][head]
#pragma unroll
    for (int nt = 0; nt < 2; nt++) {
        scor[(w * 16 + g) * 17 + nt * 8 + t4 * 2 + 0] = d[nt][0];
        scor[(w * 16 + g) * 17 + nt * 8 + t4 * 2 + 1] = d[nt][1];
        scor[(w * 16 + g + 8) * 17 + nt * 8 + t4 * 2 + 0] = d[nt][2];
        scor[(w * 16 + g + 8) * 17 + nt * 8 + t4 * 2 + 1] = d[nt][3];
    }
    __syncthreads();

    // softmax over heads + att store (tf32-rounded); head (tid&15) is
    // loop-invariant -> accumulate A locally, one smem atomic at the end.
    float* attb = g_att + ((size_t)b * SEQ + row0) * HN;
    float a_loc = 0.f;
#pragma unroll
    for (int it = 0; it < 8; it++) {
        const int row = it * 16 + (tid >> 4);
        const int hh  = tid & 15;
        float sc = scor[row * 17 + hh] + c_s[hh];
        float m = sc;
#pragma unroll
        for (int o = 8; o > 0; o >>= 1) m = fmaxf(m, __shfl_xor_sync(~0u, m, o));
        float e = __expf(sc - m);
        float sum = e;
#pragma unroll
        for (int o = 8; o > 0; o >>= 1) sum += __shfl_xor_sync(~0u, sum, o);
        float att = __fdividef(e, sum);
        attb[row * HN + hh] = __uint_as_float(f2tf32(att));
        a_loc += att;
    }
    atomicAdd(&A_s[tid & 15], a_loc);
    __syncthreads();
    if (tid < HN) atomicAdd(&g_A[b * HN + tid], A_s[tid]);
}

// ---------------------------------------------------------------------------
// K3b SCALAR (R9-proven, 71.4us): u[b,h,j] += sum_s att[b,s,h]*value[b,s,j]
//  grid (16 chunks, 16 b), 256 thr, 2 CTA/SM, f32x2 FMA accumulators.
// ---------------------------------------------------------------------------
__global__ __launch_bounds__(256, 2)
void k3b_accum(const float* __restrict__ value) {
    __shared__ unsigned long long att_s[512];   // 32 rows x 16 heads, packed {a,a}

    const int b = blockIdx.y;
    const int chunk = blockIdx.x;
    const int tid = threadIdx.x;
    const int wq = tid >> 5;
    const int lane = tid & 31;
    const int j0 = (wq << 7) + (lane << 2);

    const float* valb = value + (size_t)b * SEQ * HDIM;
    const float* attb = g_att + (size_t)b * SEQ * HN;
    const int row0 = chunk << 8;

    unsigned long long u2[32];
#pragma unroll
    for (int i = 0; i < 32; i++) u2[i] = 0ULL;

    for (int G = 0; G < 8; G++) {
        const int r32 = row0 + G * 32;
        {
            const float* asrc = attb + (size_t)r32 * HN;
            att_s[tid]       = pack_dup(asrc[tid]);
            att_s[tid + 256] = pack_dup(asrc[tid + 256]);
        }
        __syncthreads();

#pragma unroll
        for (int g4 = 0; g4 < 4; g4++) {
            const int rb = r32 + g4 * 8;
            ulonglong2 vv[8];
#pragma unroll
            for (int r = 0; r < 8; r++)
                vv[r] = *(const ulonglong2*)(valb + (size_t)(rb + r) * HDIM + j0);
#pragma unroll
            for (int r = 0; r < 8; r++) {
#pragma unroll
                for (int h = 0; h < 16; h++) {
                    unsigned long long a2 = att_s[(g4 * 8 + r) * 16 + h];
                    fma2(u2[2 * h + 0], a2, vv[r].x);
                    fma2(u2[2 * h + 1], a2, vv[r].y);
                }
            }
        }
        __syncthreads();
    }

    float* ubase = g_u + (b * HN) * HDIM + j0;
#pragma unroll
    for (int h = 0; h < 16; h++) {
        float2 lo = unpack2(u2[2 * h + 0]);
        float2 hi = unpack2(u2[2 * h + 1]);
        atomicAdd(ubase + (h << 10) + 0, lo.x);
        atomicAdd(ubase + (h << 10) + 1, lo.y);
        atomicAdd(ubase + (h << 10) + 2, hi.x);
        atomicAdd(ubase + (h << 10) + 3, hi.y);
    }
}

// ---------------------------------------------------------------------------
// K4 v2: o1[b,j] = Wv[j,:] . u[b, j/64, :] + bv[j] * A[b, j/64]
//  warp per (j, b-half): Wv row register-resident, reused over 8 batches.
// ---------------------------------------------------------------------------
__global__ void k4_out(const float* __restrict__ Wv,
                       const float* __restrict__ bv) {
    int gw   = (blockIdx.x * blockDim.x + threadIdx.x) >> 5;
    int lane = threadIdx.x & 31;
    if (gw >= HDIM * 2) return;
    int j = gw >> 1, bh = gw & 1, h = j >> 6;
    float4 wv[8];
    const float4* wr = (const float4*)(Wv + (size_t)j * HDIM);
#pragma unroll
    for (int t = 0; t < 8; t++) wv[t] = wr[t * 32 + lane];
    float bvj = bv[j];
#pragma unroll
    for (int bb = 0; bb < 8; bb++) {
        int b = bh * 8 + bb;
        const float4* ur = (const float4*)(g_u + (size_t)(b * HN + h) * HDIM);
        float acc = 0.f;
#pragma unroll
        for (int t = 0; t < 8; t++) {
            float4 u = ur[t * 32 + lane];
            acc += wv[t].x * u.x + wv[t].y * u.y + wv[t].z * u.z + wv[t].w * u.w;
        }
#pragma unroll
        for (int o = 16; o > 0; o >>= 1) acc += __shfl_xor_sync(~0u, acc, o);
        if (lane == 0) g_o1[b * HDIM + j] = acc + bvj * g_A[b * HN + h];
    }
}

// ---------------------------------------------------------------------------
// K5 v2: res[b,i] = Wf[i,:] . o1[b,:] + bf[i]
//  warp per (i, b-half): Wf row register-resident, reused over 8 batches.
// ---------------------------------------------------------------------------
__global__ void k5_final(const float* __restrict__ Wf,
                         const float* __restrict__ bf,
                         float* __restrict__ res) {
    int gw   = (blockIdx.x * blockDim.x + threadIdx.x) >> 5;
    int lane = threadIdx.x & 31;
    if (gw >= HDIM * 2) return;
    int i = gw >> 1, bh = gw & 1;
    float4 wf[8];
    const float4* wr = (const float4*)(Wf + (size_t)i * HDIM);
#pragma unroll
    for (int t = 0; t < 8; t++) wf[t] = wr[t * 32 + lane];
    float bfi = bf[i];
#pragma unroll
    for (int bb = 0; bb < 8; bb++) {
        int b = bh * 8 + bb;
        const float4* orow = (const float4*)(g_o1 + (size_t)b * HDIM);
        float acc = 0.f;
#pragma unroll
        for (int t = 0; t < 8; t++) {
            float4 o = orow[t * 32 + lane];
            acc += wf[t].x * o.x + wf[t].y * o.y + wf[t].z * o.z + wf[t].w * o.w;
        }
#pragma unroll
        for (int o = 16; o > 0; o >>= 1) acc += __shfl_xor_sync(~0u, acc, o);
        if (lane == 0) res[b * HDIM + i] = acc + bfi;
    }
}

// ---------------------------------------------------------------------------
// launch (single stream; proven pipeline)
// ---------------------------------------------------------------------------
extern "C" void kernel_launch(void* const* d_in, const int* in_sizes, int n_in,
                              void* d_out, int out_size) {
    const float* query = (const float*)d_in[0];
    const float* key_  = (const float*)d_in[1];
    const float* value = (const float*)d_in[2];
    const float* Wq    = (const float*)d_in[3];
    const float* bq    = (const float*)d_in[4];
    const float* Wk    = (const float*)d_in[5];
    const float* bk    = (const float*)d_in[6];
    const float* Wv    = (const float*)d_in[7];
    const float* bv    = (const float*)d_in[8];
    const float* Wf    = (const float*)d_in[9];
    const float* bf    = (const float*)d_in[10];
    float* out = (float*)d_out;

    const int k3a_smem = (3 * 128 * KTS + 3 * 32 * WTS + 128 * 17 + 32) * 4;  // 73344 B
    static bool attr_set = false;
    if (!attr_set) {
        cudaFuncSetAttribute(k3a_scores, cudaFuncAttributeMaxDynamicSharedMemorySize, k3a_smem);
        attr_set = true;
    }

    k1_q<<<(HDIM * 2 * 32 + 255) / 256, 256>>>(query, Wq, bq);
    k2_w<<<HN * BATCH, 256>>>(Wk, bk);
    {
        dim3 grid_a(SEQ / 128, BATCH);
        k3a_scores<<<grid_a, 256, k3a_smem>>>(key_);
        dim3 grid_b(SEQ / 256, BATCH);
        k3b_accum<<<grid_b, 256>>>(value);
    }
    k4_out<<<(HDIM * 2 * 32 + 255) / 256, 256>>>(Wv, bv);
    k5_final<<<(HDIM * 2 * 32 + 255) / 256, 256>>>(Wf, bf, out);
}